// round 1
// baseline (speedup 1.0000x reference)
#include <cuda_runtime.h>

#define H 128
#define W 128
#define NCONV 8
#define TILE_ROWS 16
#define FROWS 18      // TILE_ROWS + 2 (halo)
#define FCOLS 136     // padded row stride; smem idx = col + 4, col in [-2..129]
#define NTHREADS 256

__device__ __forceinline__ unsigned long long pk2(float lo, float hi) {
    unsigned long long r;
    asm("mov.b64 %0, {%1, %2};" : "=l"(r) : "f"(lo), "f"(hi));
    return r;
}
__device__ __forceinline__ void fma2(unsigned long long &d, unsigned long long a, unsigned long long b) {
    asm("fma.rn.f32x2 %0, %1, %2, %0;" : "+l"(d) : "l"(a), "l"(b));
}
__device__ __forceinline__ void upk2(unsigned long long v, float &lo, float &hi) {
    asm("mov.b64 {%0, %1}, %2;" : "=f"(lo), "=f"(hi) : "l"(v));
}

__global__ void __launch_bounds__(NTHREADS, 2)
kan_conv_kernel(const float* __restrict__ x,
                const float* __restrict__ cheby,
                const float* __restrict__ bw,
                const float* __restrict__ ss,
                float* __restrict__ out)
{
    // feature maps: [feat][row][col+4]; feat 0=silu 1=t 2=T2 3=T3
    __shared__ __align__(16) float featsm[4][FROWS][FCOLS];
    // weights duplicated into both f32x2 lanes: [(tap*4+feat)*8 + j]
    __shared__ __align__(16) unsigned long long wsm[9 * 4 * 8];
    __shared__ __align__(16) unsigned long long biasd[NCONV];

    const int tid = threadIdx.x;
    const int blk = blockIdx.x;
    const int bc  = blk >> 3;                  // plane index b*C + c (0..255)
    const int r0  = (blk & 7) * TILE_ROWS;     // tile top row

    // ---- weights -> smem (as duplicated pairs) ----
    for (int idx = tid; idx < 9 * 4 * 8; idx += NTHREADS) {
        int j   = idx & 7;
        int fi  = idx >> 3;       // tap*4 + f
        int tap = fi >> 2;
        int f   = fi & 3;
        float wv;
        if (f == 0) wv = bw[j * 9 + tap];                                  // base (silu) weight
        else        wv = cheby[(j * 9 + tap) * 4 + f] * ss[j * 9 + tap];   // T1..T3 weight
        wsm[idx] = pk2(wv, wv);
    }
    if (tid < NCONV) {
        float s = 0.f;
        #pragma unroll
        for (int i = 0; i < 9; i++) s += cheby[(tid * 9 + i) * 4] * ss[tid * 9 + i]; // T0 bias
        biasd[tid] = pk2(s, s);
    }

    // ---- feature maps into smem (halo rows/cols get zero-input features) ----
    const float* xp = x + (size_t)bc * (H * W);
    for (int idx = tid; idx < FROWS * 130; idx += NTHREADS) {
        int lr = idx / 130;
        int c  = idx - lr * 130 - 1;          // c in [-1, 128]
        int gr = r0 - 1 + lr;                 // global row
        float s, t, t2, t3;
        if ((unsigned)gr < H && (unsigned)c < W) {
            float xv  = xp[gr * W + c];
            float sig = __fdividef(1.f, 1.f + __expf(-xv));
            s = xv * sig;
            float em = __expf(-2.f * fabsf(xv));
            float tt = __fdividef(1.f - em, 1.f + em);
            t  = copysignf(tt, xv);
            t2 = fmaf(t + t, t, -1.f);
            t3 = fmaf(t + t, t2, -t);
        } else {
            // features of literal 0 input (zero padding): T2(0) = -1 !
            s = 0.f; t = 0.f; t2 = -1.f; t3 = 0.f;
        }
        featsm[0][lr][c + 4] = s;
        featsm[1][lr][c + 4] = t;
        featsm[2][lr][c + 4] = t2;
        featsm[3][lr][c + 4] = t3;
    }
    __syncthreads();

    // ---- compute: each thread -> 4 cols x 2 rows x 8 j = 64 outputs ----
    const int lx = tid & 31;
    const int ty = tid >> 5;       // 0..7
    const int x0 = lx * 4;         // 0..124
    const int yb = ty * 2;         // local output rows yb, yb+1

    unsigned long long acc[8][4];  // [j][r*2 + px]  (px: col pair 0 -> x0..x0+1, 1 -> x0+2..x0+3)
    #pragma unroll
    for (int j = 0; j < 8; j++) {
        unsigned long long b = biasd[j];
        acc[j][0] = b; acc[j][1] = b; acc[j][2] = b; acc[j][3] = b;
    }

    #pragma unroll
    for (int dy = 0; dy < 3; dy++) {
        #pragma unroll
        for (int f = 0; f < 4; f++) {
            unsigned long long pa[2][5];   // packed pairs (s[k-1], s[k]) for k = 0..4 (rel. to x0)
            #pragma unroll
            for (int r = 0; r < 2; r++) {
                const float* p = &featsm[f][yb + dy + r][x0 + 2];   // = smem idx of col x0-2
                float2 a  = *(const float2*)p;        // s[-2], s[-1]
                float4 bq = *(const float4*)(p + 2);  // s[0]..s[3]  (16B aligned)
                float  cq = p[6];                     // s[4]
                pa[r][0] = pk2(a.y,  bq.x);
                pa[r][1] = pk2(bq.x, bq.y);
                pa[r][2] = pk2(bq.y, bq.z);
                pa[r][3] = pk2(bq.z, bq.w);
                pa[r][4] = pk2(bq.w, cq);
            }
            #pragma unroll
            for (int dx = 0; dx < 3; dx++) {
                const ulonglong2* wp = (const ulonglong2*)&wsm[((dy * 3 + dx) * 4 + f) * 8];
                ulonglong2 w01 = wp[0], w23 = wp[1], w45 = wp[2], w67 = wp[3];
                #pragma unroll
                for (int r = 0; r < 2; r++) {
                    unsigned long long f0 = pa[r][dx];      // pair (x0+dx-1, x0+dx)
                    unsigned long long f1 = pa[r][dx + 2];  // pair (x0+dx+1, x0+dx+2)
                    fma2(acc[0][r*2+0], f0, w01.x); fma2(acc[0][r*2+1], f1, w01.x);
                    fma2(acc[1][r*2+0], f0, w01.y); fma2(acc[1][r*2+1], f1, w01.y);
                    fma2(acc[2][r*2+0], f0, w23.x); fma2(acc[2][r*2+1], f1, w23.x);
                    fma2(acc[3][r*2+0], f0, w23.y); fma2(acc[3][r*2+1], f1, w23.y);
                    fma2(acc[4][r*2+0], f0, w45.x); fma2(acc[4][r*2+1], f1, w45.x);
                    fma2(acc[5][r*2+0], f0, w45.y); fma2(acc[5][r*2+1], f1, w45.y);
                    fma2(acc[6][r*2+0], f0, w67.x); fma2(acc[6][r*2+1], f1, w67.x);
                    fma2(acc[7][r*2+0], f0, w67.y); fma2(acc[7][r*2+1], f1, w67.y);
                }
            }
        }
    }

    // ---- store (STG.128, coalesced) ----
    const int orow = r0 + yb;
    float* ob = out + ((size_t)(bc * NCONV) * H + orow) * W + x0;
    #pragma unroll
    for (int j = 0; j < 8; j++) {
        #pragma unroll
        for (int r = 0; r < 2; r++) {
            float4 v;
            upk2(acc[j][2 * r + 0], v.x, v.y);
            upk2(acc[j][2 * r + 1], v.z, v.w);
            *(float4*)(ob + ((size_t)j * H + r) * W) = v;
        }
    }
}

extern "C" void kernel_launch(void* const* d_in, const int* in_sizes, int n_in,
                              void* d_out, int out_size) {
    const float* x     = (const float*)d_in[0];
    const float* cheby = (const float*)d_in[1];   // (8, 9, 4)
    const float* bw    = (const float*)d_in[2];   // (8, 9)
    const float* ss    = (const float*)d_in[3];   // (8, 9)
    float* out = (float*)d_out;

    const int planes = 16 * 16;                   // B * C
    dim3 grid(planes * (H / TILE_ROWS));          // 2048 blocks
    kan_conv_kernel<<<grid, NTHREADS>>>(x, cheby, bw, ss, out);
}